// round 1
// baseline (speedup 1.0000x reference)
#include <cuda_runtime.h>
#include <cstring>

// CVXPolicy_Integrator: ustar = -scale(p) * p,  p = tanh([t,z]@W1+b1)@W2 + b2
// B=131072, D=256, H=100. Two fused-GEMM kernels, fp32 with packed fma.rn.f32x2.

#define Bq   131072
#define Dq   256
#define Hq   100
#define TM   64          // rows per block tile
#define NT   256         // threads per block

// scratch for hidden activations [B][100]
__device__ float g_H[(size_t)Bq * Hq];

// ---------------- helpers ----------------
union F2U { float2 f; unsigned long long u; };

__device__ __forceinline__ float2 f2fma(float2 a, float2 b, float2 c) {
    F2U A, Bv, C, Dd;
    A.f = a; Bv.f = b; C.f = c;
    asm("fma.rn.f32x2 %0, %1, %2, %3;" : "=l"(Dd.u) : "l"(A.u), "l"(Bv.u), "l"(C.u));
    return Dd.f;
}
__device__ __forceinline__ float2 splat2(float x) { return make_float2(x, x); }

// accurate-enough tanh: 1 MUFU (EX2) + Newton reciprocal on FMA pipe. |err| ~1e-6 abs.
__device__ __forceinline__ float tanh_fast(float x) {
    float ax = fabsf(x);
    float e  = __expf(-2.0f * ax);            // (0,1]
    float y  = 1.0f + e;                      // (1,2]
    float r  = __uint_as_float(0x7EF311C3u - __float_as_uint(y));
    r = r * (2.0f - y * r);
    r = r * (2.0f - y * r);
    r = r * (2.0f - y * r);                   // 1/y to ~full precision
    float th = fmaf(-2.0f * e, r, 1.0f);      // (1-e)/(1+e)
    return copysignf(th, x);
}

// ---------------- kernel 1: h = tanh([z,t]@W1 + b1) ----------------
// smem: w1s[257*100 + 28 pad] (rows rotated: w1s row i = W1 row i+1, row 256 = W1 row 0,
//       so xs can hold z at i=0..255 and t at i=256), xs[64][260]
#define W1S_ELEMS 25728
#define XS_STRIDE 260
#define SMEM1 ((W1S_ELEMS + TM * XS_STRIDE) * 4)

__global__ void __launch_bounds__(NT, 1)
k1_hidden(const float* __restrict__ z, const float* __restrict__ t,
          const float* __restrict__ W1, const float* __restrict__ b1)
{
    extern __shared__ float sm[];
    float* w1s = sm;
    float* xs  = sm + W1S_ELEMS;
    const int tid  = threadIdx.x;
    const int tile = blockIdx.x;

    // load W1 rotated: w1s[0..25599] = W1[100..25699] (rows 1..256), w1s[25600..25699] = W1 row 0
    {
        const float4* wsrc = (const float4*)(W1 + Hq);     // 400B offset, 16B aligned
        float4*       wdst = (float4*)w1s;
        #pragma unroll 4
        for (int k = tid; k < 6400; k += NT) wdst[k] = wsrc[k];
        if (tid < Hq) w1s[25600 + tid] = W1[tid];
        if (tid < 28) w1s[25700 + tid] = 0.0f;             // pad (over-read region)
    }
    // load z tile transposed-free (row-major, stride 260), t at column 256
    {
        const float4* zg = (const float4*)(z + (size_t)tile * TM * Dq);
        #pragma unroll 4
        for (int k = tid; k < TM * 64; k += NT) {
            int r = k >> 6, c4 = k & 63;
            *(float4*)&xs[r * XS_STRIDE + 4 * c4] = zg[k];
        }
        if (tid < TM) xs[tid * XS_STRIDE + 256] = t[(size_t)tile * TM + tid];
    }
    __syncthreads();

    const int warp = tid >> 5, lane = tid & 31;
    const int r0 = warp * 8;

    float2 acc0[8], acc1[8];
    #pragma unroll
    for (int r = 0; r < 8; r++) { acc0[r] = make_float2(0.f, 0.f); acc1[r] = make_float2(0.f, 0.f); }

    const float* wcol = w1s + 2 * lane;   // pair0 = cols {2l,2l+1}, pair1 = cols {64+2l,65+2l}
    #pragma unroll 1
    for (int i = 0; i < 256; i += 4) {
        const float* wb = wcol + i * Hq;
        float2 w0a = *(const float2*)(wb);
        float2 w0b = *(const float2*)(wb + 64);
        float2 w1a = *(const float2*)(wb + 100);
        float2 w1b = *(const float2*)(wb + 164);
        float2 w2a = *(const float2*)(wb + 200);
        float2 w2b = *(const float2*)(wb + 264);
        float2 w3a = *(const float2*)(wb + 300);
        float2 w3b = *(const float2*)(wb + 364);
        #pragma unroll
        for (int r = 0; r < 8; r++) {
            float4 x4 = *(const float4*)&xs[(r0 + r) * XS_STRIDE + i];
            float2 sx = splat2(x4.x);
            acc0[r] = f2fma(sx, w0a, acc0[r]);  acc1[r] = f2fma(sx, w0b, acc1[r]);
            float2 sy = splat2(x4.y);
            acc0[r] = f2fma(sy, w1a, acc0[r]);  acc1[r] = f2fma(sy, w1b, acc1[r]);
            float2 sz = splat2(x4.z);
            acc0[r] = f2fma(sz, w2a, acc0[r]);  acc1[r] = f2fma(sz, w2b, acc1[r]);
            float2 sw = splat2(x4.w);
            acc0[r] = f2fma(sw, w3a, acc0[r]);  acc1[r] = f2fma(sw, w3b, acc1[r]);
        }
    }
    { // tail i = 256 (the t column; w1s row 256 = W1 row 0)
        const float* wb = wcol + 256 * Hq;
        float2 wa = *(const float2*)(wb);
        float2 wbv = *(const float2*)(wb + 64);
        #pragma unroll
        for (int r = 0; r < 8; r++) {
            float2 sx = splat2(xs[(r0 + r) * XS_STRIDE + 256]);
            acc0[r] = f2fma(sx, wa, acc0[r]);
            acc1[r] = f2fma(sx, wbv, acc1[r]);
        }
    }

    // epilogue: bias + tanh + store (pair1 valid only for lanes < 18: cols 64+2l < 100)
    const bool v1 = (lane < 18);
    float2 bp0 = __ldg((const float2*)b1 + lane);
    float2 bp1 = v1 ? __ldg((const float2*)b1 + 32 + lane) : make_float2(0.f, 0.f);
    #pragma unroll
    for (int r = 0; r < 8; r++) {
        size_t row = (size_t)tile * TM + r0 + r;
        float2 h0;
        h0.x = tanh_fast(acc0[r].x + bp0.x);
        h0.y = tanh_fast(acc0[r].y + bp0.y);
        *(float2*)&g_H[row * Hq + 2 * lane] = h0;
        if (v1) {
            float2 h1;
            h1.x = tanh_fast(acc1[r].x + bp1.x);
            h1.y = tanh_fast(acc1[r].y + bp1.y);
            *(float2*)&g_H[row * Hq + 64 + 2 * lane] = h1;
        }
    }
}

// ---------------- kernel 2: p = h@W2 + b2 ; Lambert-Newton ; ustar ----------------
// smem: w2s[100*256] + hs[64*100]
#define SMEM2 ((Hq * Dq + TM * Hq) * 4)

__global__ void __launch_bounds__(NT, 1)
k2_policy(const float* __restrict__ W2, const float* __restrict__ b2,
          float* __restrict__ out)
{
    extern __shared__ float sm2[];
    float* w2s = sm2;
    float* hs  = sm2 + Hq * Dq;
    const int tid  = threadIdx.x;
    const int tile = blockIdx.x;

    {
        const float4* ws = (const float4*)W2;
        float4* wd = (float4*)w2s;
        #pragma unroll 4
        for (int k = tid; k < (Hq * Dq) / 4; k += NT) wd[k] = ws[k];
        const float4* hg = (const float4*)(g_H + (size_t)tile * TM * Hq);
        float4* hd = (float4*)hs;
        #pragma unroll 4
        for (int k = tid; k < (TM * Hq) / 4; k += NT) hd[k] = hg[k];
    }
    __syncthreads();

    const int warp = tid >> 5, lane = tid & 31;
    const int r0 = warp * 8;

    float2 acc[8][4];   // col pairs {2l,2l+1} + 64*j
    #pragma unroll
    for (int r = 0; r < 8; r++)
        #pragma unroll
        for (int j = 0; j < 4; j++) acc[r][j] = make_float2(0.f, 0.f);

    #pragma unroll 1
    for (int i = 0; i < Hq; i += 2) {
        const float* wb0 = w2s + i * Dq + 2 * lane;
        const float* wb1 = wb0 + Dq;
        float2 wa[4], wbv[4];
        #pragma unroll
        for (int j = 0; j < 4; j++) {
            wa[j]  = *(const float2*)(wb0 + 64 * j);
            wbv[j] = *(const float2*)(wb1 + 64 * j);
        }
        #pragma unroll
        for (int r = 0; r < 8; r++) {
            float2 h2 = *(const float2*)&hs[(r0 + r) * Hq + i];
            float2 ha = splat2(h2.x);
            float2 hb = splat2(h2.y);
            #pragma unroll
            for (int j = 0; j < 4; j++) acc[r][j] = f2fma(ha, wa[j], acc[r][j]);
            #pragma unroll
            for (int j = 0; j < 4; j++) acc[r][j] = f2fma(hb, wbv[j], acc[r][j]);
        }
    }

    // bias
    float2 bj[4];
    #pragma unroll
    for (int j = 0; j < 4; j++) bj[j] = __ldg((const float2*)b2 + 32 * j + lane);
    #pragma unroll
    for (int r = 0; r < 8; r++)
        #pragma unroll
        for (int j = 0; j < 4; j++) {
            acc[r][j].x += bj[j].x;
            acc[r][j].y += bj[j].y;
        }

    // r2 per row -> lane r holds row r's r2
    float myr2 = 0.0f;
    #pragma unroll
    for (int r = 0; r < 8; r++) {
        float s = 0.0f;
        #pragma unroll
        for (int j = 0; j < 4; j++) {
            s = fmaf(acc[r][j].x, acc[r][j].x, s);
            s = fmaf(acc[r][j].y, acc[r][j].y, s);
        }
        #pragma unroll
        for (int o = 16; o > 0; o >>= 1) s += __shfl_xor_sync(0xffffffffu, s, o);
        if (lane == r) myr2 = s;
    }

    // Lambert-W Newton (exactly the reference recurrence, 30 iters). Lanes 8..31 run on r2=0 (benign).
    float w = log1pf(myr2);
    #pragma unroll
    for (int it = 0; it < 30; it++) {
        float ew  = __expf(w);
        float num = fmaf(w, ew, -myr2);         // w*e^w - r2
        float den = fmaf(w, ew, ew);            // (1+w)*e^w
        w = w - __fdividef(num, den);
    }
    w = fmaxf(w, 0.0f);
    float tn = sqrtf(w);
    float rr = sqrtf(myr2);
    float scale = (rr > 1e-12f) ? __fdividef(tn, fmaxf(rr, 1e-12f)) : 1.0f;

    // store ustar = -scale * p
    #pragma unroll
    for (int r = 0; r < 8; r++) {
        float sc = -__shfl_sync(0xffffffffu, scale, r);
        float* orow = out + ((size_t)tile * TM + r0 + r) * Dq;
        #pragma unroll
        for (int j = 0; j < 4; j++) {
            float2 v;
            v.x = sc * acc[r][j].x;
            v.y = sc * acc[r][j].y;
            *(float2*)&orow[64 * j + 2 * lane] = v;
        }
    }
}

// ---------------- launch ----------------
extern "C" void kernel_launch(void* const* d_in, const int* in_sizes, int n_in,
                              void* d_out, int out_size)
{
    const float* z  = (const float*)d_in[0];
    const float* t  = (const float*)d_in[1];
    const float* W1 = (const float*)d_in[2];
    const float* b1 = (const float*)d_in[3];
    const float* W2 = (const float*)d_in[4];
    const float* b2 = (const float*)d_in[5];
    float* out = (float*)d_out;

    cudaFuncSetAttribute(k1_hidden, cudaFuncAttributeMaxDynamicSharedMemorySize, SMEM1);
    cudaFuncSetAttribute(k2_policy, cudaFuncAttributeMaxDynamicSharedMemorySize, SMEM2);

    const int nblk = Bq / TM;   // 2048
    k1_hidden<<<nblk, NT, SMEM1>>>(z, t, W1, b1);
    k2_policy<<<nblk, NT, SMEM2>>>(W2, b2, out);
}

// round 2
// speedup vs baseline: 1.4894x; 1.4894x over previous
#include <cuda_runtime.h>

// CVXPolicy_Integrator via tf32 mma.sync (tensor pipe), two fused kernels.
// B=131072, D=256, H=100.
// k1: h = tanh([z,t]@W1 + b1), stored tf32-rounded, padded to 104 cols.
// k2: p = h@W2 + b2; r2=||p||^2; LambertW Newton; ustar = -(tn/r) p.

#define Bq 131072
#define Dq 256
#define Hq 100

// ---- GEMM1 geometry ----
#define KP1   264          // padded K (256 z + 1 t + 7 zero), 33 k-steps
#define NP1   104          // padded N (100 + 4 zero), 13 n-tiles
#define SW1   268          // w1t row stride (bank-conflict-free quad pattern)
#define SX1   36           // xs row stride
#define NT    256

// ---- GEMM2 geometry ----
#define KP2   104          // padded K (100 + 4 zero), 13 k-steps
#define SW2   108          // w2t / hs row stride

// hidden activations, tf32 bit patterns, [B][104]
__device__ unsigned g_H[(size_t)Bq * NP1];

// ---------------- helpers ----------------
__device__ __forceinline__ unsigned cvt_tf32(float f) {
    unsigned u;
    asm("cvt.rna.tf32.f32 %0, %1;" : "=r"(u) : "f"(f));
    return u;
}

__device__ __forceinline__ void mma_tf32(float* c,
                                         unsigned a0, unsigned a1, unsigned a2, unsigned a3,
                                         unsigned b0, unsigned b1) {
    asm volatile(
        "mma.sync.aligned.m16n8k8.row.col.f32.tf32.tf32.f32 "
        "{%0,%1,%2,%3}, {%4,%5,%6,%7}, {%8,%9}, {%0,%1,%2,%3};"
        : "+f"(c[0]), "+f"(c[1]), "+f"(c[2]), "+f"(c[3])
        : "r"(a0), "r"(a1), "r"(a2), "r"(a3), "r"(b0), "r"(b1));
}

// 1 MUFU + Newton reciprocal tanh, |err| ~1e-6
__device__ __forceinline__ float tanh_fast(float x) {
    float ax = fabsf(x);
    float e  = __expf(-2.0f * ax);
    float y  = 1.0f + e;
    float r  = __uint_as_float(0x7EF311C3u - __float_as_uint(y));
    r = r * (2.0f - y * r);
    r = r * (2.0f - y * r);
    r = r * (2.0f - y * r);
    float th = fmaf(-2.0f * e, r, 1.0f);
    return copysignf(th, x);
}

// ---------------- kernel 1 ----------------
// smem: w1t[104][268] (u32 tf32) + xs[2][128][36] + b1s[104]
#define SM1_W  (NP1 * SW1)          // 27872
#define SM1_X  (2 * 128 * SX1)      // 9216
#define SMEM1  ((SM1_W + SM1_X + NP1) * 4)

__global__ void __launch_bounds__(NT, 1)
k1_hidden(const float* __restrict__ z, const float* __restrict__ t,
          const float* __restrict__ W1, const float* __restrict__ b1)
{
    extern __shared__ unsigned sm[];
    unsigned* w1t = sm;
    unsigned* xs  = sm + SM1_W;
    float*    b1s = (float*)(sm + SM1_W + SM1_X);

    const int tid  = threadIdx.x;
    const int tile = blockIdx.x;

    // W1 transpose + reorder: X columns are [z(0..255), t(256)], so X-col kk<256
    // pairs with W1 row kk+1; X-col 256 pairs with W1 row 0. w1t[n][kk].
    for (int idx = tid; idx < 257 * Hq; idx += NT) {
        int k = idx / Hq, n = idx - k * Hq;          // gmem coalesced (100-wide rows)
        int kk = (k == 0) ? 256 : (k - 1);
        w1t[n * SW1 + kk] = cvt_tf32(W1[idx]);
    }
    // pads: n in [100,104) all k; n<100, k in [257,264)
    for (int idx = tid; idx < 4 * KP1; idx += NT) {
        int n = 100 + idx / KP1, k = idx % KP1;
        w1t[n * SW1 + k] = 0u;
    }
    for (int idx = tid; idx < Hq * 7; idx += NT) {
        int n = idx / 7, k = 257 + idx % 7;
        w1t[n * SW1 + k] = 0u;
    }
    if (tid < NP1) b1s[tid] = (tid < 100) ? b1[tid] : 0.0f;

    const int warp = tid >> 5, lane = tid & 31;
    const int gid = lane >> 2, tig = lane & 3;
    const int m0 = warp * 16;

    float4 rg[4];
    const float4* zsrc = (const float4*)(z + (size_t)tile * (128 * Dq));

    // stage chunk 0 (z cols 0..31)
    #pragma unroll
    for (int j = 0; j < 4; j++) {
        int q = j * NT + tid; int r = q >> 3, c4 = q & 7;
        rg[j] = zsrc[(size_t)r * 64 + c4];
    }
    #pragma unroll
    for (int j = 0; j < 4; j++) {
        int q = j * NT + tid; int r = q >> 3, c4 = q & 7;
        unsigned* d = xs + r * SX1 + c4 * 4;
        d[0] = cvt_tf32(rg[j].x); d[1] = cvt_tf32(rg[j].y);
        d[2] = cvt_tf32(rg[j].z); d[3] = cvt_tf32(rg[j].w);
    }
    __syncthreads();

    float acc[13][4];
    #pragma unroll
    for (int nt = 0; nt < 13; nt++)
        #pragma unroll
        for (int i = 0; i < 4; i++) acc[nt][i] = 0.0f;

    for (int c = 0; c < 9; c++) {
        // prefetch next chunk into regs (overlaps mma below)
        if (c < 8) {
            if (c < 7) {
                #pragma unroll
                for (int j = 0; j < 4; j++) {
                    int q = j * NT + tid; int r = q >> 3, c4 = q & 7;
                    rg[j] = zsrc[(size_t)r * 64 + (c + 1) * 8 + c4];
                }
            } else { // chunk 8: t column at local col 0, zeros elsewhere
                #pragma unroll
                for (int j = 0; j < 4; j++) {
                    int q = j * NT + tid; int r = q >> 3, c4 = q & 7;
                    float v = (c4 == 0) ? t[tile * 128 + r] : 0.0f;
                    rg[j] = make_float4(v, 0.0f, 0.0f, 0.0f);
                }
            }
        }

        const unsigned* xb = xs + (c & 1) * (128 * SX1);
        const int ksteps = (c == 8) ? 1 : 4;
        for (int ks = 0; ks < ksteps; ks++) {
            int k0 = ks * 8;
            unsigned a0 = xb[(m0 + gid)     * SX1 + k0 + tig];
            unsigned a1 = xb[(m0 + gid + 8) * SX1 + k0 + tig];
            unsigned a2 = xb[(m0 + gid)     * SX1 + k0 + tig + 4];
            unsigned a3 = xb[(m0 + gid + 8) * SX1 + k0 + tig + 4];
            int kg = c * 32 + k0;
            #pragma unroll
            for (int nt = 0; nt < 13; nt++) {
                unsigned b0 = w1t[(nt * 8 + gid) * SW1 + kg + tig];
                unsigned b1v = w1t[(nt * 8 + gid) * SW1 + kg + tig + 4];
                mma_tf32(acc[nt], a0, a1, a2, a3, b0, b1v);
            }
        }

        if (c < 8) {
            unsigned* d0 = xs + ((c + 1) & 1) * (128 * SX1);
            #pragma unroll
            for (int j = 0; j < 4; j++) {
                int q = j * NT + tid; int r = q >> 3, c4 = q & 7;
                unsigned* d = d0 + r * SX1 + c4 * 4;
                d[0] = cvt_tf32(rg[j].x); d[1] = cvt_tf32(rg[j].y);
                d[2] = cvt_tf32(rg[j].z); d[3] = cvt_tf32(rg[j].w);
            }
        }
        __syncthreads();
    }

    // epilogue: bias + tanh + tf32-round + store
    const size_t row0 = (size_t)tile * 128 + m0 + gid;
    const size_t row1 = row0 + 8;
    #pragma unroll
    for (int nt = 0; nt < 13; nt++) {
        int col = nt * 8 + 2 * tig;
        float bb0 = b1s[col], bb1 = b1s[col + 1];
        uint2 u;
        u.x = cvt_tf32(tanh_fast(acc[nt][0] + bb0));
        u.y = cvt_tf32(tanh_fast(acc[nt][1] + bb1));
        *(uint2*)&g_H[row0 * NP1 + col] = u;
        u.x = cvt_tf32(tanh_fast(acc[nt][2] + bb0));
        u.y = cvt_tf32(tanh_fast(acc[nt][3] + bb1));
        *(uint2*)&g_H[row1 * NP1 + col] = u;
    }
}

// ---------------- kernel 2 ----------------
// smem: w2t[256][108] + hs[64][108] + b2s[256] + r2p[2][64] + scs[64]
#define SM2_W  (Dq * SW2)       // 27648
#define SM2_H  (64 * SW2)       // 6912
#define SMEM2  ((SM2_W + SM2_H + Dq + 128 + 64) * 4)

__global__ void __launch_bounds__(NT, 1)
k2_policy(const float* __restrict__ W2, const float* __restrict__ b2,
          float* __restrict__ out)
{
    extern __shared__ unsigned sm2[];
    unsigned* w2t = sm2;
    unsigned* hs  = sm2 + SM2_W;
    float*    b2s = (float*)(sm2 + SM2_W + SM2_H);
    float*    r2p = b2s + Dq;      // [2][64]
    float*    scs = r2p + 128;     // [64]

    const int tid  = threadIdx.x;
    const int tile = blockIdx.x;

    // W2 transpose: w2t[n][k] = W2[k][n], zero pad k in [100,104)
    for (int idx = tid; idx < Hq * Dq; idx += NT) {
        int k = idx >> 8, n = idx & 255;             // gmem coalesced
        w2t[n * SW2 + k] = cvt_tf32(W2[idx]);
    }
    for (int idx = tid; idx < Dq * 4; idx += NT) {
        int n = idx & 255, k = 100 + (idx >> 8);
        w2t[n * SW2 + k] = 0u;
    }
    // h tile [64][104] -> smem stride 108 (already tf32 bits)
    {
        const uint4* hg = (const uint4*)(g_H + (size_t)tile * (64 * NP1));
        for (int idx = tid; idx < 64 * 26; idx += NT) {
            int r = idx / 26, c4 = idx % 26;
            *(uint4*)&hs[r * SW2 + 4 * c4] = hg[r * 26 + c4];
        }
    }
    if (tid < Dq) b2s[tid] = b2[tid];
    __syncthreads();

    const int warp = tid >> 5, lane = tid & 31;
    const int gid = lane >> 2, tig = lane & 3;
    const int m0 = (warp & 3) * 16;
    const int n0 = (warp >> 2) * 128;
    const int hh = warp >> 2;

    float acc[16][4];
    #pragma unroll
    for (int nt = 0; nt < 16; nt++)
        #pragma unroll
        for (int i = 0; i < 4; i++) acc[nt][i] = 0.0f;

    #pragma unroll 1
    for (int ks = 0; ks < 13; ks++) {
        int k0 = ks * 8;
        unsigned a0 = hs[(m0 + gid)     * SW2 + k0 + tig];
        unsigned a1 = hs[(m0 + gid + 8) * SW2 + k0 + tig];
        unsigned a2 = hs[(m0 + gid)     * SW2 + k0 + tig + 4];
        unsigned a3 = hs[(m0 + gid + 8) * SW2 + k0 + tig + 4];
        #pragma unroll
        for (int nt = 0; nt < 16; nt++) {
            unsigned b0 = w2t[(n0 + nt * 8 + gid) * SW2 + k0 + tig];
            unsigned b1v = w2t[(n0 + nt * 8 + gid) * SW2 + k0 + tig + 4];
            mma_tf32(acc[nt], a0, a1, a2, a3, b0, b1v);
        }
    }

    // bias + per-row partial ||p||^2
    float s0 = 0.0f, s2 = 0.0f;
    #pragma unroll
    for (int nt = 0; nt < 16; nt++) {
        int col = n0 + nt * 8 + 2 * tig;
        float b0f = b2s[col], b1f = b2s[col + 1];
        acc[nt][0] += b0f; acc[nt][1] += b1f;
        acc[nt][2] += b0f; acc[nt][3] += b1f;
        s0 = fmaf(acc[nt][0], acc[nt][0], s0);
        s0 = fmaf(acc[nt][1], acc[nt][1], s0);
        s2 = fmaf(acc[nt][2], acc[nt][2], s2);
        s2 = fmaf(acc[nt][3], acc[nt][3], s2);
    }
    s0 += __shfl_xor_sync(0xffffffffu, s0, 1);
    s0 += __shfl_xor_sync(0xffffffffu, s0, 2);
    s2 += __shfl_xor_sync(0xffffffffu, s2, 1);
    s2 += __shfl_xor_sync(0xffffffffu, s2, 2);
    if (tig == 0) {
        r2p[hh * 64 + m0 + gid]     = s0;
        r2p[hh * 64 + m0 + gid + 8] = s2;
    }
    __syncthreads();

    // Lambert-W Newton per row (64 rows/block), reference recurrence, 30 iters
    if (tid < 64) {
        float r2 = r2p[tid] + r2p[64 + tid];
        float w = log1pf(r2);
        #pragma unroll
        for (int it = 0; it < 30; it++) {
            float ew  = __expf(w);
            float num = fmaf(w, ew, -r2);
            float den = fmaf(w, ew, ew);
            w = w - __fdividef(num, den);
        }
        w = fmaxf(w, 0.0f);
        float tn = sqrtf(w);
        float rr = sqrtf(r2);
        float scale = (rr > 1e-12f) ? __fdividef(tn, fmaxf(rr, 1e-12f)) : 1.0f;
        scs[tid] = -scale;
    }
    __syncthreads();

    // store ustar = -scale * p
    const float sc0 = scs[m0 + gid];
    const float sc2 = scs[m0 + gid + 8];
    const size_t rb0 = ((size_t)tile * 64 + m0 + gid) * Dq;
    const size_t rb1 = rb0 + (size_t)8 * Dq;
    #pragma unroll
    for (int nt = 0; nt < 16; nt++) {
        int col = n0 + nt * 8 + 2 * tig;
        *(float2*)&out[rb0 + col] = make_float2(sc0 * acc[nt][0], sc0 * acc[nt][1]);
        *(float2*)&out[rb1 + col] = make_float2(sc2 * acc[nt][2], sc2 * acc[nt][3]);
    }
}

// ---------------- launch ----------------
extern "C" void kernel_launch(void* const* d_in, const int* in_sizes, int n_in,
                              void* d_out, int out_size)
{
    const float* z  = (const float*)d_in[0];
    const float* t  = (const float*)d_in[1];
    const float* W1 = (const float*)d_in[2];
    const float* b1 = (const float*)d_in[3];
    const float* W2 = (const float*)d_in[4];
    const float* b2 = (const float*)d_in[5];
    float* out = (float*)d_out;

    cudaFuncSetAttribute(k1_hidden, cudaFuncAttributeMaxDynamicSharedMemorySize, SMEM1);
    cudaFuncSetAttribute(k2_policy, cudaFuncAttributeMaxDynamicSharedMemorySize, SMEM2);

    k1_hidden<<<Bq / 128, NT, SMEM1>>>(z, t, W1, b1);
    k2_policy<<<Bq / 64,  NT, SMEM2>>>(W2, b2, out);
}

// round 3
// speedup vs baseline: 2.6036x; 1.7480x over previous
#include <cuda_runtime.h>

// CVXPolicy_Integrator, persistent tf32-mma version.
// k1: h = tanh([z,t]@W1+b1) -> g_H (tf32 bits, [B][104])
// k2: p = h@W2+b2; r2; LambertW Newton; ustar = -(tn/r) p
// Both kernels: grid=148 persistent CTAs, 512 threads, weights in smem once.

#define Bq    131072
#define Dq    256
#define Hq    100
#define GRID  148
#define NT    512

#define NP1   104      // padded H
#define SW1   268      // w1t row stride (words)
#define KP1   264      // padded K for GEMM1
#define SW2   108      // w2t / hs row stride (words)
#define XSW   36       // xs row stride (words)
#define XBUF  (128 * XSW)
#define NTILES (Bq / 128)   // 1024

__device__ unsigned g_H[(size_t)Bq * NP1];

// ---------------- helpers ----------------
__device__ __forceinline__ unsigned cvt_tf32(float f) {
    unsigned u;
    asm("cvt.rna.tf32.f32 %0, %1;" : "=r"(u) : "f"(f));
    return u;
}
__device__ __forceinline__ void mma_tf32(float* c,
                                         unsigned a0, unsigned a1, unsigned a2, unsigned a3,
                                         unsigned b0, unsigned b1) {
    asm volatile(
        "mma.sync.aligned.m16n8k8.row.col.f32.tf32.tf32.f32 "
        "{%0,%1,%2,%3}, {%4,%5,%6,%7}, {%8,%9}, {%0,%1,%2,%3};"
        : "+f"(c[0]), "+f"(c[1]), "+f"(c[2]), "+f"(c[3])
        : "r"(a0), "r"(a1), "r"(a2), "r"(a3), "r"(b0), "r"(b1));
}
__device__ __forceinline__ void cp_async16(void* sdst, const void* gsrc) {
    unsigned s = (unsigned)__cvta_generic_to_shared(sdst);
    asm volatile("cp.async.cg.shared.global [%0], [%1], 16;" :: "r"(s), "l"(gsrc));
}
#define CP_COMMIT() asm volatile("cp.async.commit_group;")
#define CP_WAIT(n)  asm volatile("cp.async.wait_group %0;" :: "n"(n))

// k-permutation inside groups of 8 so B-frag pairs {k, k+4} sit adjacent (LDS.64)
__device__ __forceinline__ int permk(int k) {
    return (k & ~7) | ((k & 3) << 1) | ((k >> 2) & 1);
}

__device__ __forceinline__ float tanh_fast(float x) {
    float ax = fabsf(x);
    float e  = __expf(-2.0f * ax);
    float y  = 1.0f + e;
    float r  = __uint_as_float(0x7EF311C3u - __float_as_uint(y));
    r = r * (2.0f - y * r);
    r = r * (2.0f - y * r);
    r = r * (2.0f - y * r);
    float th = fmaf(-2.0f * e, r, 1.0f);
    return copysignf(th, x);
}

// ---------------- kernel 1 ----------------
// smem: w1t[104][268] + xs[3][128][36] + b1s[104]
#define SMEM1 ((NP1 * SW1 + 3 * XBUF + NP1) * 4)

__global__ void __launch_bounds__(NT, 1)
k1_hidden(const float* __restrict__ z, const float* __restrict__ t,
          const float* __restrict__ W1, const float* __restrict__ b1)
{
    extern __shared__ unsigned sm[];
    unsigned* w1t = sm;
    unsigned* xs  = sm + NP1 * SW1;
    float*    b1s = (float*)(sm + NP1 * SW1 + 3 * XBUF);

    const int tid = threadIdx.x;

    // ---- one-time weight load: transpose + k-rotate + k-perm ----
    // X cols = [z0..z255, t]; X-col kk<256 pairs W1 row kk+1; kk=256 pairs W1 row 0.
    for (int idx = tid; idx < 257 * Hq; idx += NT) {
        int k = idx / Hq, n = idx - k * Hq;
        int kk = (k == 0) ? 256 : (k - 1);
        w1t[n * SW1 + permk(kk)] = cvt_tf32(W1[idx]);
    }
    for (int idx = tid; idx < NP1 * 7; idx += NT) {      // k-pad 257..263 (perm positions)
        int n = idx / 7, j = idx - n * 7;
        w1t[n * SW1 + 257 + j] = 0u;
    }
    for (int idx = tid; idx < 4 * KP1; idx += NT) {      // n-pad rows 100..103
        int n = 100 + idx / KP1, j = idx % KP1;
        w1t[n * SW1 + j] = 0u;
    }
    if (tid < NP1) b1s[tid] = (tid < Hq) ? b1[tid] : 0.0f;

    const int warp = tid >> 5, lane = tid & 31;
    const int gid = lane >> 2, tig = lane & 3;
    const int m0  = (warp & 7) * 16;
    const int ng  = warp >> 3;
    const int ncb = ng * 56;
    const int ntc = ng ? 6 : 7;

    // ---- chunk-stream prefetch state (chunks: 8 z-chunks of 32 cols + 1 t-chunk) ----
    int pt = blockIdx.x;   // tile being prefetched
    int pc = 0;            // chunk within tile
    int pb = 0;            // destination buffer

    #define K1_ISSUE() do {                                                          \
        unsigned* dst = xs + pb * XBUF;                                              \
        if (pt < NTILES) {                                                           \
            if (pc < 8) {                                                            \
                const float4* src = (const float4*)z + ((size_t)pt * 128) * 64 + pc * 8; \
                _Pragma("unroll")                                                    \
                for (int j = 0; j < 2; j++) {                                        \
                    int q = j * NT + tid; int r = q >> 3, c4 = q & 7;                \
                    cp_async16(dst + r * XSW + c4 * 4, src + (size_t)r * 64 + c4);   \
                }                                                                    \
            } else {                                                                 \
                int r = tid >> 2, qq = tid & 3;                                      \
                unsigned* d = dst + r * XSW + qq * 8;                                \
                uint4 zz = make_uint4(0u, 0u, 0u, 0u);                               \
                *(uint4*)(d) = zz; *(uint4*)(d + 4) = zz;                            \
                if (qq == 0) d[0] = __float_as_uint(t[pt * 128 + r]);                \
            }                                                                        \
        }                                                                            \
        CP_COMMIT();                                                                 \
        pc++; if (pc == 9) { pc = 0; pt += GRID; }                                   \
        pb++; if (pb == 3) pb = 0;                                                   \
    } while (0)

    K1_ISSUE();
    K1_ISSUE();
    __syncthreads();    // w1t/b1s visible (prefetches still in flight)

    float acc[7][4];
    #pragma unroll
    for (int nt = 0; nt < 7; nt++)
        #pragma unroll
        for (int i = 0; i < 4; i++) acc[nt][i] = 0.0f;

    int bi = 0;
    for (int tile = blockIdx.x; tile < NTILES; tile += GRID) {
        for (int cc = 0; cc < 9; cc++) {
            CP_WAIT(1);          // chunk (tile,cc) landed
            __syncthreads();     // ...and visible; prior mma on reissue target done
            K1_ISSUE();          // prefetch chunk +2 into ring

            const float* xb = (const float*)(xs + bi * XBUF);
            const int kst = (cc == 8) ? 1 : 4;
            for (int ks = 0; ks < kst; ks++) {
                int k0 = ks * 8;
                unsigned a0 = cvt_tf32(xb[(m0 + gid)     * XSW + k0 + tig]);
                unsigned a1 = cvt_tf32(xb[(m0 + gid + 8) * XSW + k0 + tig]);
                unsigned a2 = cvt_tf32(xb[(m0 + gid)     * XSW + k0 + tig + 4]);
                unsigned a3 = cvt_tf32(xb[(m0 + gid + 8) * XSW + k0 + tig + 4]);
                int kg = cc * 32 + k0;
                #pragma unroll
                for (int nt = 0; nt < 7; nt++) {
                    if (nt < ntc) {
                        uint2 bb = *(const uint2*)&w1t[(ncb + nt * 8 + gid) * SW1 + kg + 2 * tig];
                        mma_tf32(acc[nt], a0, a1, a2, a3, bb.x, bb.y);
                    }
                }
            }
            bi++; if (bi == 3) bi = 0;
        }

        // epilogue: bias + tanh + tf32 store
        size_t row0 = (size_t)tile * 128 + m0 + gid;
        #pragma unroll
        for (int nt = 0; nt < 7; nt++) {
            if (nt < ntc) {
                int col = ncb + nt * 8 + 2 * tig;
                float bb0 = b1s[col], bb1 = b1s[col + 1];
                uint2 u;
                u.x = cvt_tf32(tanh_fast(acc[nt][0] + bb0));
                u.y = cvt_tf32(tanh_fast(acc[nt][1] + bb1));
                *(uint2*)&g_H[row0 * NP1 + col] = u;
                u.x = cvt_tf32(tanh_fast(acc[nt][2] + bb0));
                u.y = cvt_tf32(tanh_fast(acc[nt][3] + bb1));
                *(uint2*)&g_H[(row0 + 8) * NP1 + col] = u;
                acc[nt][0] = acc[nt][1] = acc[nt][2] = acc[nt][3] = 0.0f;
            }
        }
    }
}

// ---------------- kernel 2 ----------------
// smem: w2t[256][108] + hs[2][128][108] + b2s[256] + r2p[2][128] + scs[128]
#define HS_OFF  (Dq * SW2)
#define HBUF    (128 * SW2)
#define SMEM2   ((Dq * SW2 + 2 * HBUF + Dq + 256 + 128) * 4)

__device__ __forceinline__ void k2_prefetch(unsigned* hbuf, int tile, int tid) {
    const uint4* src = (const uint4*)(g_H + (size_t)tile * 128 * NP1);
    #pragma unroll
    for (int j = 0; j < 7; j++) {
        int idx = j * NT + tid;
        if (idx < 128 * 26) {
            int r = idx / 26, c = idx - r * 26;
            cp_async16(hbuf + r * SW2 + c * 4, src + r * 26 + c);
        }
    }
}

__global__ void __launch_bounds__(NT, 1)
k2_policy(const float* __restrict__ W2, const float* __restrict__ b2,
          float* __restrict__ out)
{
    extern __shared__ unsigned sm2[];
    unsigned* w2t = sm2;
    unsigned* hs  = sm2 + HS_OFF;
    float*    b2s = (float*)(sm2 + HS_OFF + 2 * HBUF);
    float*    r2p = b2s + Dq;
    float*    scs = r2p + 256;

    const int tid = threadIdx.x;

    // one-time W2 transpose (k-permuted)
    for (int idx = tid; idx < Hq * Dq; idx += NT) {
        int k = idx >> 8, n = idx & 255;
        w2t[n * SW2 + permk(k)] = cvt_tf32(W2[idx]);
    }
    for (int idx = tid; idx < Dq * 4; idx += NT) {   // k-pad 100..103 -> perm positions 97,99,101,103
        int n = idx >> 2, j = idx & 3;
        w2t[n * SW2 + 97 + 2 * j] = 0u;
    }
    if (tid < Dq) b2s[tid] = b2[tid];

    int pt = blockIdx.x;
    k2_prefetch(hs, pt, tid);
    CP_COMMIT();
    __syncthreads();

    const int warp = tid >> 5, lane = tid & 31;
    const int gid = lane >> 2, tig = lane & 3;
    const int m0 = (warp & 7) * 16;
    const int nh = warp >> 3;
    const int n0 = nh * 128;

    int bi = 0;
    for (int tile = blockIdx.x; tile < NTILES; tile += GRID) {
        CP_WAIT(0);
        __syncthreads();
        if (tile + GRID < NTILES) k2_prefetch(hs + (bi ^ 1) * HBUF, tile + GRID, tid);
        CP_COMMIT();

        const unsigned* hb = hs + bi * HBUF;
        float acc[16][4];
        #pragma unroll
        for (int nt = 0; nt < 16; nt++)
            #pragma unroll
            for (int i = 0; i < 4; i++) acc[nt][i] = 0.0f;

        #pragma unroll 1
        for (int ks = 0; ks < 13; ks++) {
            int k0 = ks * 8;
            unsigned a0 = hb[(m0 + gid)     * SW2 + k0 + tig];
            unsigned a1 = hb[(m0 + gid + 8) * SW2 + k0 + tig];
            unsigned a2 = hb[(m0 + gid)     * SW2 + k0 + tig + 4];
            unsigned a3 = hb[(m0 + gid + 8) * SW2 + k0 + tig + 4];
            #pragma unroll
            for (int nt = 0; nt < 16; nt++) {
                uint2 bb = *(const uint2*)&w2t[(n0 + nt * 8 + gid) * SW2 + k0 + 2 * tig];
                mma_tf32(acc[nt], a0, a1, a2, a3, bb.x, bb.y);
            }
        }

        // bias + partial ||p||^2
        float s0 = 0.0f, s2 = 0.0f;
        #pragma unroll
        for (int nt = 0; nt < 16; nt++) {
            int col = n0 + nt * 8 + 2 * tig;
            float b0f = b2s[col], b1f = b2s[col + 1];
            acc[nt][0] += b0f; acc[nt][1] += b1f;
            acc[nt][2] += b0f; acc[nt][3] += b1f;
            s0 = fmaf(acc[nt][0], acc[nt][0], s0);
            s0 = fmaf(acc[nt][1], acc[nt][1], s0);
            s2 = fmaf(acc[nt][2], acc[nt][2], s2);
            s2 = fmaf(acc[nt][3], acc[nt][3], s2);
        }
        s0 += __shfl_xor_sync(0xffffffffu, s0, 1);
        s0 += __shfl_xor_sync(0xffffffffu, s0, 2);
        s2 += __shfl_xor_sync(0xffffffffu, s2, 1);
        s2 += __shfl_xor_sync(0xffffffffu, s2, 2);
        if (tig == 0) {
            r2p[nh * 128 + m0 + gid]     = s0;
            r2p[nh * 128 + m0 + gid + 8] = s2;
        }
        __syncthreads();

        // Lambert-W Newton (converged well before 10 iters; start above root)
        if (tid < 128) {
            float r2 = r2p[tid] + r2p[128 + tid];
            float w = log1pf(r2);
            #pragma unroll
            for (int it = 0; it < 10; it++) {
                float ew  = __expf(w);
                float num = fmaf(w, ew, -r2);
                float den = fmaf(w, ew, ew);
                w = w - __fdividef(num, den);
            }
            w = fmaxf(w, 0.0f);
            float tn = sqrtf(w);
            float rr = sqrtf(r2);
            float scale = (rr > 1e-12f) ? __fdividef(tn, fmaxf(rr, 1e-12f)) : 1.0f;
            scs[tid] = -scale;
        }
        __syncthreads();

        const float sc0 = scs[m0 + gid];
        const float sc2 = scs[m0 + gid + 8];
        const size_t rb0 = ((size_t)tile * 128 + m0 + gid) * Dq;
        const size_t rb1 = rb0 + (size_t)8 * Dq;
        #pragma unroll
        for (int nt = 0; nt < 16; nt++) {
            int col = n0 + nt * 8 + 2 * tig;
            *(float2*)&out[rb0 + col] = make_float2(sc0 * acc[nt][0], sc0 * acc[nt][1]);
            *(float2*)&out[rb1 + col] = make_float2(sc2 * acc[nt][2], sc2 * acc[nt][3]);
        }
        bi ^= 1;
    }
}

// ---------------- launch ----------------
extern "C" void kernel_launch(void* const* d_in, const int* in_sizes, int n_in,
                              void* d_out, int out_size)
{
    const float* z  = (const float*)d_in[0];
    const float* t  = (const float*)d_in[1];
    const float* W1 = (const float*)d_in[2];
    const float* b1 = (const float*)d_in[3];
    const float* W2 = (const float*)d_in[4];
    const float* b2 = (const float*)d_in[5];
    float* out = (float*)d_out;

    cudaFuncSetAttribute(k1_hidden, cudaFuncAttributeMaxDynamicSharedMemorySize, SMEM1);
    cudaFuncSetAttribute(k2_policy, cudaFuncAttributeMaxDynamicSharedMemorySize, SMEM2);

    k1_hidden<<<GRID, NT, SMEM1>>>(z, t, W1, b1);
    k2_policy<<<GRID, NT, SMEM2>>>(W2, b2, out);
}

// round 4
// speedup vs baseline: 3.0230x; 1.1611x over previous
#include <cuda_runtime.h>

// CVXPolicy_Integrator, persistent tf32-mma, round 4:
// conflict-free smem strides (==8 mod 32), m32 warp tiles (half B traffic),
// k-permuted layouts so all fragment loads are LDS.64.

#define Bq    131072
#define Dq    256
#define Hq    100
#define GRID  148
#define NT    512
#define NTILES (Bq / 128)   // 1024

#define NP1   104      // padded H (k-dim of GEMM2, n-dim of GEMM1)
#define SW1   264      // w1t row stride, 264 % 32 == 8 -> conflict-free
#define XSW   40       // xs row stride,  40 % 32 == 8
#define XBUF  (128 * XSW)
#define SW2   104      // w2t/hs row stride, 104 % 32 == 8 (dense for hs!)

// hidden activations, tf32 bits, k-PERMUTED columns, [B][104]
__device__ unsigned g_H[(size_t)Bq * NP1];

// ---------------- helpers ----------------
__device__ __forceinline__ unsigned cvt_tf32(float f) {
    unsigned u;
    asm("cvt.rna.tf32.f32 %0, %1;" : "=r"(u) : "f"(f));
    return u;
}
__device__ __forceinline__ void mma_tf32(float* c,
                                         unsigned a0, unsigned a1, unsigned a2, unsigned a3,
                                         unsigned b0, unsigned b1) {
    asm volatile(
        "mma.sync.aligned.m16n8k8.row.col.f32.tf32.tf32.f32 "
        "{%0,%1,%2,%3}, {%4,%5,%6,%7}, {%8,%9}, {%0,%1,%2,%3};"
        : "+f"(c[0]), "+f"(c[1]), "+f"(c[2]), "+f"(c[3])
        : "r"(a0), "r"(a1), "r"(a2), "r"(a3), "r"(b0), "r"(b1));
}
__device__ __forceinline__ void cp_async16(void* sdst, const void* gsrc) {
    unsigned s = (unsigned)__cvta_generic_to_shared(sdst);
    asm volatile("cp.async.cg.shared.global [%0], [%1], 16;" :: "r"(s), "l"(gsrc));
}
#define CP_COMMIT() asm volatile("cp.async.commit_group;")
#define CP_WAIT(n)  asm volatile("cp.async.wait_group %0;" :: "n"(n))

// within each 8-block: position(b) = (b&3)<<1 | b>>2, so {k, k+4} -> {2t, 2t+1}
__device__ __forceinline__ int permk(int k) {
    return (k & ~7) | ((k & 3) << 1) | ((k >> 2) & 1);
}

__device__ __forceinline__ float tanh_fast(float x) {
    float ax = fabsf(x);
    float e  = __expf(-2.0f * ax);
    float y  = 1.0f + e;
    float r  = __uint_as_float(0x7EF311C3u - __float_as_uint(y));
    r = r * (2.0f - y * r);
    r = r * (2.0f - y * r);
    r = r * (2.0f - y * r);
    float th = fmaf(-2.0f * e, r, 1.0f);
    return copysignf(th, x);
}

// ---------------- kernel 1: h = tanh([z,t]@W1+b1) ----------------
// smem: w1t[104][264] + xs[3][128][40] + b1s[104]   (~172 KB)
#define SMEM1 ((NP1 * SW1 + 3 * XBUF + NP1) * 4)

__global__ void __launch_bounds__(NT, 1)
k1_hidden(const float* __restrict__ z, const float* __restrict__ t,
          const float* __restrict__ W1, const float* __restrict__ b1)
{
    extern __shared__ unsigned sm[];
    unsigned* w1t = sm;
    unsigned* xs  = sm + NP1 * SW1;
    float*    b1s = (float*)(sm + NP1 * SW1 + 3 * XBUF);

    const int tid = threadIdx.x;

    // one-time: W1 transpose + k-rotate (t at k=256) + k-perm
    for (int idx = tid; idx < 257 * Hq; idx += NT) {
        int k = idx / Hq, n = idx - k * Hq;
        int kk = (k == 0) ? 256 : (k - 1);
        w1t[n * SW1 + permk(kk)] = cvt_tf32(W1[idx]);
    }
    for (int idx = tid; idx < NP1 * 7; idx += NT) {      // k-pad 257..263
        int n = idx / 7, j = idx - n * 7;
        w1t[n * SW1 + 257 + j] = 0u;
    }
    for (int idx = tid; idx < 4 * SW1; idx += NT) {      // n-pad rows 100..103
        int n = 100 + idx / SW1, j = idx % SW1;
        w1t[n * SW1 + j] = 0u;
    }
    if (tid < NP1) b1s[tid] = (tid < Hq) ? b1[tid] : 0.0f;

    const int warp = tid >> 5, lane = tid & 31;
    const int gid = lane >> 2, tig = lane & 3;
    const int m0  = (warp & 3) * 32;                 // 4 m-groups of 32 rows
    const int ng  = warp >> 2;                       // 4 n-groups
    const int tb  = ng ? (1 + 3 * ng) : 0;           // tile bases {0,4,7,10}
    const int ntc = ng ? 3 : 4;                      // tile counts {4,3,3,3}

    // chunk-stream prefetch (8 z-chunks of 32 cols + 1 t-chunk), ring of 3
    int pt = blockIdx.x, pc = 0, pb = 0;

    #define K1_ISSUE() do {                                                          \
        unsigned* dst = xs + pb * XBUF;                                              \
        if (pt < NTILES) {                                                           \
            if (pc < 8) {                                                            \
                const float4* src = (const float4*)z + ((size_t)pt * 128) * 64 + pc * 8; \
                _Pragma("unroll")                                                    \
                for (int j = 0; j < 2; j++) {                                        \
                    int q = j * NT + tid; int r = q >> 3, c4 = q & 7;                \
                    cp_async16(dst + r * XSW + c4 * 4, src + (size_t)r * 64 + c4);   \
                }                                                                    \
            } else {                                                                 \
                int r = tid >> 2, qq = tid & 3;                                      \
                unsigned* d = dst + r * XSW + qq * 8;                                \
                uint4 zz = make_uint4(0u, 0u, 0u, 0u);                               \
                *(uint4*)(d) = zz; *(uint4*)(d + 4) = zz;                            \
                if (qq == 0) d[0] = __float_as_uint(t[pt * 128 + r]);                \
            }                                                                        \
        }                                                                            \
        CP_COMMIT();                                                                 \
        pc++; if (pc == 9) { pc = 0; pt += GRID; }                                   \
        pb++; if (pb == 3) pb = 0;                                                   \
    } while (0)

    K1_ISSUE();
    K1_ISSUE();
    __syncthreads();

    float acc[4][2][4];
    #pragma unroll
    for (int nt = 0; nt < 4; nt++)
        #pragma unroll
        for (int mf = 0; mf < 2; mf++)
            #pragma unroll
            for (int i = 0; i < 4; i++) acc[nt][mf][i] = 0.0f;

    int bi = 0;
    const int mr = m0 + gid;
    for (int tile = blockIdx.x; tile < NTILES; tile += GRID) {
        for (int cc = 0; cc < 9; cc++) {
            CP_WAIT(1);
            __syncthreads();
            K1_ISSUE();

            const float* xb = (const float*)(xs + bi * XBUF);
            const int kst = (cc == 8) ? 1 : 4;
            for (int ks = 0; ks < kst; ks++) {
                int k0 = ks * 8;
                unsigned a0 = cvt_tf32(xb[mr * XSW + k0 + tig]);
                unsigned a1 = cvt_tf32(xb[(mr + 8) * XSW + k0 + tig]);
                unsigned a2 = cvt_tf32(xb[mr * XSW + k0 + tig + 4]);
                unsigned a3 = cvt_tf32(xb[(mr + 8) * XSW + k0 + tig + 4]);
                unsigned a4 = cvt_tf32(xb[(mr + 16) * XSW + k0 + tig]);
                unsigned a5 = cvt_tf32(xb[(mr + 24) * XSW + k0 + tig]);
                unsigned a6 = cvt_tf32(xb[(mr + 16) * XSW + k0 + tig + 4]);
                unsigned a7 = cvt_tf32(xb[(mr + 24) * XSW + k0 + tig + 4]);
                int kg = cc * 32 + k0;
                #pragma unroll
                for (int nt = 0; nt < 4; nt++) {
                    if (nt < ntc) {
                        uint2 bb = *(const uint2*)&w1t[((tb + nt) * 8 + gid) * SW1 + kg + 2 * tig];
                        mma_tf32(acc[nt][0], a0, a1, a2, a3, bb.x, bb.y);
                        mma_tf32(acc[nt][1], a4, a5, a6, a7, bb.x, bb.y);
                    }
                }
            }
            bi++; if (bi == 3) bi = 0;
        }

        // epilogue: bias + tanh + store k-PERMUTED columns to g_H
        size_t rowb = (size_t)tile * 128 + mr;
        #pragma unroll
        for (int nt = 0; nt < 4; nt++) {
            if (nt < ntc) {
                int col = (tb + nt) * 8 + 2 * tig;
                float bb0 = b1s[col], bb1 = b1s[col + 1];
                int c0 = permk(col), c1 = permk(col + 1);
                #pragma unroll
                for (int mf = 0; mf < 2; mf++) {
                    size_t r0 = rowb + mf * 16;
                    g_H[r0 * NP1 + c0]       = cvt_tf32(tanh_fast(acc[nt][mf][0] + bb0));
                    g_H[r0 * NP1 + c1]       = cvt_tf32(tanh_fast(acc[nt][mf][1] + bb1));
                    g_H[(r0 + 8) * NP1 + c0] = cvt_tf32(tanh_fast(acc[nt][mf][2] + bb0));
                    g_H[(r0 + 8) * NP1 + c1] = cvt_tf32(tanh_fast(acc[nt][mf][3] + bb1));
                    acc[nt][mf][0] = acc[nt][mf][1] = acc[nt][mf][2] = acc[nt][mf][3] = 0.0f;
                }
            }
        }
    }
}

// ---------------- kernel 2 ----------------
// smem: w2t[256][104] + hs[2][128][104] + b2s[256] + r2p[4][128] + scs[128]  (~217 KB)
#define HBUF  (128 * SW2)
#define SMEM2 ((Dq * SW2 + 2 * HBUF + Dq + 512 + 128) * 4)

__device__ __forceinline__ void k2_prefetch(unsigned* hbuf, int tile, int tid) {
    const uint4* src = (const uint4*)(g_H + (size_t)tile * 128 * NP1);
    #pragma unroll
    for (int j = 0; j < 7; j++) {
        int idx = j * NT + tid;
        if (idx < 128 * 26) cp_async16(hbuf + idx * 4, src + idx);   // dense: SW2==NP1
    }
}

__global__ void __launch_bounds__(NT, 1)
k2_policy(const float* __restrict__ W2, const float* __restrict__ b2,
          float* __restrict__ out)
{
    extern __shared__ unsigned sm2[];
    unsigned* w2t = sm2;
    unsigned* hs  = sm2 + Dq * SW2;
    float*    b2s = (float*)(sm2 + Dq * SW2 + 2 * HBUF);
    float*    r2p = b2s + Dq;      // [4][128]
    float*    scs = r2p + 512;     // [128]

    const int tid = threadIdx.x;

    // one-time W2 transpose (k-permuted)
    for (int idx = tid; idx < Hq * Dq; idx += NT) {
        int k = idx >> 8, n = idx & 255;
        w2t[n * SW2 + permk(k)] = cvt_tf32(W2[idx]);
    }
    for (int idx = tid; idx < Dq * 4; idx += NT) {   // k-pad 100..103 -> positions 97,99,101,103
        int n = idx >> 2, j = idx & 3;
        w2t[n * SW2 + 97 + 2 * j] = 0u;
    }
    if (tid < Dq) b2s[tid] = b2[tid];

    k2_prefetch(hs, blockIdx.x, tid);
    CP_COMMIT();
    __syncthreads();

    const int warp = tid >> 5, lane = tid & 31;
    const int gid = lane >> 2, tig = lane & 3;
    const int m0 = (warp & 3) * 32;
    const int ng = warp >> 2;
    const int n0 = ng * 64;
    const int mr = m0 + gid;

    int bi = 0;
    for (int tile = blockIdx.x; tile < NTILES; tile += GRID) {
        CP_WAIT(0);
        __syncthreads();
        if (tile + GRID < NTILES) k2_prefetch(hs + (bi ^ 1) * HBUF, tile + GRID, tid);
        CP_COMMIT();

        const unsigned* hb = hs + bi * HBUF;
        float acc[8][2][4];
        #pragma unroll
        for (int nt = 0; nt < 8; nt++)
            #pragma unroll
            for (int mf = 0; mf < 2; mf++)
                #pragma unroll
                for (int i = 0; i < 4; i++) acc[nt][mf][i] = 0.0f;

        #pragma unroll 1
        for (int ks = 0; ks < 13; ks++) {
            int k0 = ks * 8;
            uint2 A0 = *(const uint2*)&hb[mr * SW2 + k0 + 2 * tig];          // {a0,a2}
            uint2 A1 = *(const uint2*)&hb[(mr + 8) * SW2 + k0 + 2 * tig];    // {a1,a3}
            uint2 A2 = *(const uint2*)&hb[(mr + 16) * SW2 + k0 + 2 * tig];
            uint2 A3 = *(const uint2*)&hb[(mr + 24) * SW2 + k0 + 2 * tig];
            #pragma unroll
            for (int nt = 0; nt < 8; nt++) {
                uint2 bb = *(const uint2*)&w2t[(n0 + nt * 8 + gid) * SW2 + k0 + 2 * tig];
                mma_tf32(acc[nt][0], A0.x, A1.x, A0.y, A1.y, bb.x, bb.y);
                mma_tf32(acc[nt][1], A2.x, A3.x, A2.y, A3.y, bb.x, bb.y);
            }
        }

        // bias + per-row partial ||p||^2
        float s0 = 0.f, s1 = 0.f, s2 = 0.f, s3 = 0.f;
        #pragma unroll
        for (int nt = 0; nt < 8; nt++) {
            int col = n0 + nt * 8 + 2 * tig;
            float b0f = b2s[col], b1f = b2s[col + 1];
            acc[nt][0][0] += b0f; acc[nt][0][1] += b1f;
            acc[nt][0][2] += b0f; acc[nt][0][3] += b1f;
            acc[nt][1][0] += b0f; acc[nt][1][1] += b1f;
            acc[nt][1][2] += b0f; acc[nt][1][3] += b1f;
            s0 = fmaf(acc[nt][0][0], acc[nt][0][0], s0); s0 = fmaf(acc[nt][0][1], acc[nt][0][1], s0);
            s1 = fmaf(acc[nt][0][2], acc[nt][0][2], s1); s1 = fmaf(acc[nt][0][3], acc[nt][0][3], s1);
            s2 = fmaf(acc[nt][1][0], acc[nt][1][0], s2); s2 = fmaf(acc[nt][1][1], acc[nt][1][1], s2);
            s3 = fmaf(acc[nt][1][2], acc[nt][1][2], s3); s3 = fmaf(acc[nt][1][3], acc[nt][1][3], s3);
        }
        s0 += __shfl_xor_sync(0xffffffffu, s0, 1); s0 += __shfl_xor_sync(0xffffffffu, s0, 2);
        s1 += __shfl_xor_sync(0xffffffffu, s1, 1); s1 += __shfl_xor_sync(0xffffffffu, s1, 2);
        s2 += __shfl_xor_sync(0xffffffffu, s2, 1); s2 += __shfl_xor_sync(0xffffffffu, s2, 2);
        s3 += __shfl_xor_sync(0xffffffffu, s3, 1); s3 += __shfl_xor_sync(0xffffffffu, s3, 2);
        if (tig == 0) {
            r2p[ng * 128 + mr]      = s0;
            r2p[ng * 128 + mr + 8]  = s1;
            r2p[ng * 128 + mr + 16] = s2;
            r2p[ng * 128 + mr + 24] = s3;
        }
        __syncthreads();

        // Lambert-W Newton (converged well before 10 iters at fp32)
        if (tid < 128) {
            float r2 = r2p[tid] + r2p[128 + tid] + r2p[256 + tid] + r2p[384 + tid];
            float w = log1pf(r2);
            #pragma unroll
            for (int it = 0; it < 10; it++) {
                float ew  = __expf(w);
                float num = fmaf(w, ew, -r2);
                float den = fmaf(w, ew, ew);
                w = w - __fdividef(num, den);
            }
            w = fmaxf(w, 0.0f);
            float tn = sqrtf(w);
            float rr = sqrtf(r2);
            float scale = (rr > 1e-12f) ? __fdividef(tn, fmaxf(rr, 1e-12f)) : 1.0f;
            scs[tid] = -scale;
        }
        __syncthreads();

        const float sc0 = scs[mr],      sc1 = scs[mr + 8];
        const float sc2 = scs[mr + 16], sc3 = scs[mr + 24];
        const size_t rb = ((size_t)tile * 128 + mr) * Dq;
        #pragma unroll
        for (int nt = 0; nt < 8; nt++) {
            int col = n0 + nt * 8 + 2 * tig;
            *(float2*)&out[rb + col]             = make_float2(sc0 * acc[nt][0][0], sc0 * acc[nt][0][1]);
            *(float2*)&out[rb + 8  * Dq + col]   = make_float2(sc1 * acc[nt][0][2], sc1 * acc[nt][0][3]);
            *(float2*)&out[rb + 16 * Dq + col]   = make_float2(sc2 * acc[nt][1][0], sc2 * acc[nt][1][1]);
            *(float2*)&out[rb + 24 * Dq + col]   = make_float2(sc3 * acc[nt][1][2], sc3 * acc[nt][1][3]);
        }
        bi ^= 1;
    }
}

// ---------------- launch ----------------
extern "C" void kernel_launch(void* const* d_in, const int* in_sizes, int n_in,
                              void* d_out, int out_size)
{
    const float* z  = (const float*)d_in[0];
    const float* t  = (const float*)d_in[1];
    const float* W1 = (const float*)d_in[2];
    const float* b1 = (const float*)d_in[3];
    const float* W2 = (const float*)d_in[4];
    const float* b2 = (const float*)d_in[5];
    float* out = (float*)d_out;

    cudaFuncSetAttribute(k1_hidden, cudaFuncAttributeMaxDynamicSharedMemorySize, SMEM1);
    cudaFuncSetAttribute(k2_policy, cudaFuncAttributeMaxDynamicSharedMemorySize, SMEM2);

    k1_hidden<<<GRID, NT, SMEM1>>>(z, t, W1, b1);
    k2_policy<<<GRID, NT, SMEM2>>>(W2, b2, out);
}

// round 5
// speedup vs baseline: 3.0822x; 1.0196x over previous
#include <cuda_runtime.h>

// CVXPolicy_Integrator, persistent tf32-mma, round 5:
// k1: staging-time cvt (4x less F2FP), LDS.64 A-frags via k-permuted staging.
// k2: fully-unrolled k-loop, hoisted base pointers -> LDS [R+imm], ALU cut.

#define Bq    131072
#define Dq    256
#define Hq    100
#define GRID  148
#define NT    512
#define NTILES (Bq / 128)   // 1024

#define NP1   104      // padded H
#define SW1   264      // w1t row stride (==8 mod 32)
#define XSW   40       // xs row stride (==8 mod 32)
#define XBUF  (128 * XSW)
#define SW2   104      // w2t/hs row stride (==8 mod 32, dense)

// hidden activations, tf32 bits, k-PERMUTED columns, [B][104]
__device__ unsigned g_H[(size_t)Bq * NP1];

// ---------------- helpers ----------------
__device__ __forceinline__ unsigned cvt_tf32(float f) {
    unsigned u;
    asm("cvt.rna.tf32.f32 %0, %1;" : "=r"(u) : "f"(f));
    return u;
}
__device__ __forceinline__ void mma_tf32(float* c,
                                         unsigned a0, unsigned a1, unsigned a2, unsigned a3,
                                         unsigned b0, unsigned b1) {
    asm volatile(
        "mma.sync.aligned.m16n8k8.row.col.f32.tf32.tf32.f32 "
        "{%0,%1,%2,%3}, {%4,%5,%6,%7}, {%8,%9}, {%0,%1,%2,%3};"
        : "+f"(c[0]), "+f"(c[1]), "+f"(c[2]), "+f"(c[3])
        : "r"(a0), "r"(a1), "r"(a2), "r"(a3), "r"(b0), "r"(b1));
}
__device__ __forceinline__ void cp_async16(void* sdst, const void* gsrc) {
    unsigned s = (unsigned)__cvta_generic_to_shared(sdst);
    asm volatile("cp.async.cg.shared.global [%0], [%1], 16;" :: "r"(s), "l"(gsrc));
}
#define CP_COMMIT() asm volatile("cp.async.commit_group;")
#define CP_WAIT(n)  asm volatile("cp.async.wait_group %0;" :: "n"(n))

// within each 8-block: position(k) = (k&3)<<1 | ((k>>2)&1); pairs {k,k+4} adjacent
__device__ __forceinline__ int permk(int k) {
    return (k & ~7) | ((k & 3) << 1) | ((k >> 2) & 1);
}

__device__ __forceinline__ float tanh_fast(float x) {
    float ax = fabsf(x);
    float e  = __expf(-2.0f * ax);
    float y  = 1.0f + e;
    float r  = __uint_as_float(0x7EF311C3u - __float_as_uint(y));
    r = r * (2.0f - y * r);
    r = r * (2.0f - y * r);
    r = r * (2.0f - y * r);
    float th = fmaf(-2.0f * e, r, 1.0f);
    return copysignf(th, x);
}

// ---------------- kernel 1: h = tanh([z,t]@W1+b1) ----------------
// smem: w1t[104][264] + xs[3][128][40] (tf32, permuted) + b1s[104]  (~172 KB)
#define SMEM1 ((NP1 * SW1 + 3 * XBUF + NP1) * 4)

__global__ void __launch_bounds__(NT, 1)
k1_hidden(const float* __restrict__ z, const float* __restrict__ t,
          const float* __restrict__ W1, const float* __restrict__ b1)
{
    extern __shared__ unsigned sm[];
    unsigned* w1t = sm;
    unsigned* xs  = sm + NP1 * SW1;
    float*    b1s = (float*)(sm + NP1 * SW1 + 3 * XBUF);

    const int tid = threadIdx.x;

    // one-time: W1 transpose + k-rotate (t at k=256) + k-perm
    for (int idx = tid; idx < 257 * Hq; idx += NT) {
        int k = idx / Hq, n = idx - k * Hq;
        int kk = (k == 0) ? 256 : (k - 1);
        w1t[n * SW1 + permk(kk)] = cvt_tf32(W1[idx]);
    }
    for (int idx = tid; idx < NP1 * 7; idx += NT) {
        int n = idx / 7, j = idx - n * 7;
        w1t[n * SW1 + 257 + j] = 0u;
    }
    for (int idx = tid; idx < 4 * SW1; idx += NT) {
        int n = 100 + idx / SW1, j = idx % SW1;
        w1t[n * SW1 + j] = 0u;
    }
    if (tid < NP1) b1s[tid] = (tid < Hq) ? b1[tid] : 0.0f;

    const int warp = tid >> 5, lane = tid & 31;
    const int gid = lane >> 2, tig = lane & 3;
    const int m0  = (warp & 3) * 32;
    const int ng  = warp >> 2;
    const int tb  = ng ? (1 + 3 * ng) : 0;
    const int ntc = ng ? 3 : 4;
    const int mr  = m0 + gid;

    // staging: thread covers row sr, 8-k-block sb of each 32-col chunk
    const int sr = tid >> 2, sb = tid & 3;

    // prefetch state: (pt, pc) = next chunk to LDG (chunks: 8 z + 1 t)
    int pt = blockIdx.x, pc = 0;
    float4 rA = make_float4(0.f, 0.f, 0.f, 0.f), rB = rA;

    #define K1_LDG() do {                                                        \
        if (pt < NTILES) {                                                       \
            if (pc < 8) {                                                        \
                const float4* src = (const float4*)z                             \
                    + ((size_t)(pt * 128 + sr)) * 64 + pc * 8 + 2 * sb;          \
                rA = src[0]; rB = src[1];                                        \
            } else {                                                             \
                rA = make_float4(0.f, 0.f, 0.f, 0.f); rB = rA;                   \
                if (sb == 0) rA.x = t[pt * 128 + sr];                            \
            }                                                                    \
        }                                                                        \
        pc++; if (pc == 9) { pc = 0; pt += GRID; }                               \
    } while (0)

    // permuted store: positions 0..7 of block = {f0,f4,f1,f5,f2,f6,f3,f7}
    #define K1_STS(bs) do {                                                      \
        unsigned* d = xs + (bs) * XBUF + sr * XSW + sb * 8;                      \
        uint4 u0, u1;                                                            \
        u0.x = cvt_tf32(rA.x); u0.y = cvt_tf32(rB.x);                            \
        u0.z = cvt_tf32(rA.y); u0.w = cvt_tf32(rB.y);                            \
        u1.x = cvt_tf32(rA.z); u1.y = cvt_tf32(rB.z);                            \
        u1.z = cvt_tf32(rA.w); u1.w = cvt_tf32(rB.w);                            \
        *(uint4*)d = u0; *(uint4*)(d + 4) = u1;                                  \
    } while (0)

    K1_LDG();          // chunk 0 -> regs
    K1_STS(0);         // chunk 0 -> buf0
    K1_LDG();          // chunk 1 -> regs
    __syncthreads();   // buf0 + weights visible

    float acc[4][2][4];
    #pragma unroll
    for (int nt = 0; nt < 4; nt++)
        #pragma unroll
        for (int mf = 0; mf < 2; mf++)
            #pragma unroll
            for (int i = 0; i < 4; i++) acc[nt][mf][i] = 0.0f;

    int bcur = 0;   // buffer holding current chunk; bnext = (bcur+1)%3
    for (int tile = blockIdx.x; tile < NTILES; tile += GRID) {
        for (int cc = 0; cc < 9; cc++) {
            int bnext = bcur + 1; if (bnext == 3) bnext = 0;
            K1_STS(bnext);      // stage chunk g+1 (stale regs harmless at end)
            K1_LDG();           // fetch chunk g+2
            __syncthreads();    // staging visible; ring safety via prior bars

            const unsigned* xa = xs + bcur * XBUF + mr * XSW + 2 * tig;
            const unsigned* wb = w1t + ((tb * 8 + gid) * SW1) + cc * 32 + 2 * tig;
            const int kst = (cc == 8) ? 1 : 4;
            #pragma unroll
            for (int ks = 0; ks < 4; ks++) {
                if (ks < kst) {
                    const int k0 = ks * 8;
                    uint2 A0 = *(const uint2*)(xa + k0);
                    uint2 A1 = *(const uint2*)(xa + 8 * XSW + k0);
                    uint2 A2 = *(const uint2*)(xa + 16 * XSW + k0);
                    uint2 A3 = *(const uint2*)(xa + 24 * XSW + k0);
                    #pragma unroll
                    for (int nt = 0; nt < 4; nt++) {
                        if (nt < ntc) {
                            uint2 bb = *(const uint2*)(wb + nt * 8 * SW1 + k0);
                            mma_tf32(acc[nt][0], A0.x, A1.x, A0.y, A1.y, bb.x, bb.y);
                            mma_tf32(acc[nt][1], A2.x, A3.x, A2.y, A3.y, bb.x, bb.y);
                        }
                    }
                }
            }
            bcur = bnext;
        }

        // epilogue: bias + tanh + store k-PERMUTED to g_H
        size_t rowb = (size_t)tile * 128 + mr;
        #pragma unroll
        for (int nt = 0; nt < 4; nt++) {
            if (nt < ntc) {
                int col = (tb + nt) * 8 + 2 * tig;
                float bb0 = b1s[col], bb1 = b1s[col + 1];
                int c0 = permk(col), c1 = permk(col + 1);
                #pragma unroll
                for (int mf = 0; mf < 2; mf++) {
                    size_t r0 = rowb + mf * 16;
                    g_H[r0 * NP1 + c0]       = cvt_tf32(tanh_fast(acc[nt][mf][0] + bb0));
                    g_H[r0 * NP1 + c1]       = cvt_tf32(tanh_fast(acc[nt][mf][1] + bb1));
                    g_H[(r0 + 8) * NP1 + c0] = cvt_tf32(tanh_fast(acc[nt][mf][2] + bb0));
                    g_H[(r0 + 8) * NP1 + c1] = cvt_tf32(tanh_fast(acc[nt][mf][3] + bb1));
                    acc[nt][mf][0] = acc[nt][mf][1] = acc[nt][mf][2] = acc[nt][mf][3] = 0.0f;
                }
            }
        }
    }
}

// ---------------- kernel 2 ----------------
// smem: w2t[256][104] + hs[2][128][104] + b2s[256] + r2p[4][128] + scs[128]
#define HBUF  (128 * SW2)
#define SMEM2 ((Dq * SW2 + 2 * HBUF + Dq + 512 + 128) * 4)

__device__ __forceinline__ void k2_prefetch(unsigned* hbuf, int tile, int tid) {
    const uint4* src = (const uint4*)(g_H + (size_t)tile * 128 * NP1);
    #pragma unroll
    for (int j = 0; j < 7; j++) {
        int idx = j * NT + tid;
        if (idx < 128 * 26) cp_async16(hbuf + idx * 4, src + idx);
    }
}

__global__ void __launch_bounds__(NT, 1)
k2_policy(const float* __restrict__ W2, const float* __restrict__ b2,
          float* __restrict__ out)
{
    extern __shared__ unsigned sm2[];
    unsigned* w2t = sm2;
    unsigned* hs  = sm2 + Dq * SW2;
    float*    b2s = (float*)(sm2 + Dq * SW2 + 2 * HBUF);
    float*    r2p = b2s + Dq;
    float*    scs = r2p + 512;

    const int tid = threadIdx.x;

    for (int idx = tid; idx < Hq * Dq; idx += NT) {
        int k = idx >> 8, n = idx & 255;
        w2t[n * SW2 + permk(k)] = cvt_tf32(W2[idx]);
    }
    for (int idx = tid; idx < Dq * 4; idx += NT) {
        int n = idx >> 2, j = idx & 3;
        w2t[n * SW2 + 97 + 2 * j] = 0u;   // pads for k=100..103
    }
    if (tid < Dq) b2s[tid] = b2[tid];

    k2_prefetch(hs, blockIdx.x, tid);
    CP_COMMIT();
    __syncthreads();

    const int warp = tid >> 5, lane = tid & 31;
    const int gid = lane >> 2, tig = lane & 3;
    const int m0 = (warp & 3) * 32;
    const int ng = warp >> 2;
    const int n0 = ng * 64;
    const int mr = m0 + gid;

    int bi = 0;
    for (int tile = blockIdx.x; tile < NTILES; tile += GRID) {
        CP_WAIT(0);
        __syncthreads();
        if (tile + GRID < NTILES) k2_prefetch(hs + (bi ^ 1) * HBUF, tile + GRID, tid);
        CP_COMMIT();

        float acc[8][2][4];
        #pragma unroll
        for (int nt = 0; nt < 8; nt++)
            #pragma unroll
            for (int mf = 0; mf < 2; mf++)
                #pragma unroll
                for (int i = 0; i < 4; i++) acc[nt][mf][i] = 0.0f;

        // hoisted bases -> all inner LDS are [R + const]
        const unsigned* ha = hs + bi * HBUF + mr * SW2 + 2 * tig;
        const unsigned* wb = w2t + (n0 + gid) * SW2 + 2 * tig;

        #pragma unroll
        for (int ks = 0; ks < 13; ks++) {
            const int k0 = ks * 8;
            uint2 A0 = *(const uint2*)(ha + k0);
            uint2 A1 = *(const uint2*)(ha + 8 * SW2 + k0);
            uint2 A2 = *(const uint2*)(ha + 16 * SW2 + k0);
            uint2 A3 = *(const uint2*)(ha + 24 * SW2 + k0);
            #pragma unroll
            for (int nt = 0; nt < 8; nt++) {
                uint2 bb = *(const uint2*)(wb + nt * 8 * SW2 + k0);
                mma_tf32(acc[nt][0], A0.x, A1.x, A0.y, A1.y, bb.x, bb.y);
                mma_tf32(acc[nt][1], A2.x, A3.x, A2.y, A3.y, bb.x, bb.y);
            }
        }

        float s0 = 0.f, s1 = 0.f, s2 = 0.f, s3 = 0.f;
        #pragma unroll
        for (int nt = 0; nt < 8; nt++) {
            int col = n0 + nt * 8 + 2 * tig;
            float b0f = b2s[col], b1f = b2s[col + 1];
            acc[nt][0][0] += b0f; acc[nt][0][1] += b1f;
            acc[nt][0][2] += b0f; acc[nt][0][3] += b1f;
            acc[nt][1][0] += b0f; acc[nt][1][1] += b1f;
            acc[nt][1][2] += b0f; acc[nt][1][3] += b1f;
            s0 = fmaf(acc[nt][0][0], acc[nt][0][0], s0); s0 = fmaf(acc[nt][0][1], acc[nt][0][1], s0);
            s1 = fmaf(acc[nt][0][2], acc[nt][0][2], s1); s1 = fmaf(acc[nt][0][3], acc[nt][0][3], s1);
            s2 = fmaf(acc[nt][1][0], acc[nt][1][0], s2); s2 = fmaf(acc[nt][1][1], acc[nt][1][1], s2);
            s3 = fmaf(acc[nt][1][2], acc[nt][1][2], s3); s3 = fmaf(acc[nt][1][3], acc[nt][1][3], s3);
        }
        s0 += __shfl_xor_sync(0xffffffffu, s0, 1); s0 += __shfl_xor_sync(0xffffffffu, s0, 2);
        s1 += __shfl_xor_sync(0xffffffffu, s1, 1); s1 += __shfl_xor_sync(0xffffffffu, s1, 2);
        s2 += __shfl_xor_sync(0xffffffffu, s2, 1); s2 += __shfl_xor_sync(0xffffffffu, s2, 2);
        s3 += __shfl_xor_sync(0xffffffffu, s3, 1); s3 += __shfl_xor_sync(0xffffffffu, s3, 2);
        if (tig == 0) {
            r2p[ng * 128 + mr]      = s0;
            r2p[ng * 128 + mr + 8]  = s1;
            r2p[ng * 128 + mr + 16] = s2;
            r2p[ng * 128 + mr + 24] = s3;
        }
        __syncthreads();

        if (tid < 128) {
            float r2 = r2p[tid] + r2p[128 + tid] + r2p[256 + tid] + r2p[384 + tid];
            float w = log1pf(r2);
            #pragma unroll
            for (int it = 0; it < 10; it++) {
                float ew  = __expf(w);
                float num = fmaf(w, ew, -r2);
                float den = fmaf(w, ew, ew);
                w = w - __fdividef(num, den);
            }
            w = fmaxf(w, 0.0f);
            float tn = sqrtf(w);
            float rr = sqrtf(r2);
            float scale = (rr > 1e-12f) ? __fdividef(tn, fmaxf(rr, 1e-12f)) : 1.0f;
            scs[tid] = -scale;
        }
        __syncthreads();

        const float sc0 = scs[mr],      sc1 = scs[mr + 8];
        const float sc2 = scs[mr + 16], sc3 = scs[mr + 24];
        const size_t rb = ((size_t)tile * 128 + mr) * Dq;
        #pragma unroll
        for (int nt = 0; nt < 8; nt++) {
            int col = n0 + nt * 8 + 2 * tig;
            *(float2*)&out[rb + col]           = make_float2(sc0 * acc[nt][0][0], sc0 * acc[nt][0][1]);
            *(float2*)&out[rb + 8  * Dq + col] = make_float2(sc1 * acc[nt][0][2], sc1 * acc[nt][0][3]);
            *(float2*)&out[rb + 16 * Dq + col] = make_float2(sc2 * acc[nt][1][0], sc2 * acc[nt][1][1]);
            *(float2*)&out[rb + 24 * Dq + col] = make_float2(sc3 * acc[nt][1][2], sc3 * acc[nt][1][3]);
        }
        bi ^= 1;
    }
}

// ---------------- launch ----------------
extern "C" void kernel_launch(void* const* d_in, const int* in_sizes, int n_in,
                              void* d_out, int out_size)
{
    const float* z  = (const float*)d_in[0];
    const float* t  = (const float*)d_in[1];
    const float* W1 = (const float*)d_in[2];
    const float* b1 = (const float*)d_in[3];
    const float* W2 = (const float*)d_in[4];
    const float* b2 = (const float*)d_in[5];
    float* out = (float*)d_out;

    cudaFuncSetAttribute(k1_hidden, cudaFuncAttributeMaxDynamicSharedMemorySize, SMEM1);
    cudaFuncSetAttribute(k2_policy, cudaFuncAttributeMaxDynamicSharedMemorySize, SMEM2);

    k1_hidden<<<GRID, NT, SMEM1>>>(z, t, W1, b1);
    k2_policy<<<GRID, NT, SMEM2>>>(W2, b2, out);
}